// round 5
// baseline (speedup 1.0000x reference)
#include <cuda_runtime.h>
#include <math.h>

#define NA 8192
#define SD 64
#define HD 128
#define CD 32
#define AD 8
#define NB 128      // fused grid (<= 148 SMs -> all resident, grid barrier safe)
#define NT 1024
#define ROWS 64     // rows per block
#define RPT 8       // rows per thread in phases 1/3 (8 column-groups of 128)

// -------- device scratch --------
__device__ float g_W2c[HD * CD];    // W2 @ Wc
__device__ float g_bc2[CD];         // b2 @ Wc + bc
__device__ float g_msum[CD];        // sum of normalized msgs
__device__ float g_hsum[HD];        // column sum of relu(P + bias_eff)
__device__ unsigned g_barA, g_barB; // grid barrier counters (reset by k0)

// ============ K0: fold W2c, bc2; zero accumulators + barriers. 32 x 128 ======
__global__ void k0(const float* __restrict__ W2, const float* __restrict__ Wc,
                   const float* __restrict__ b2, const float* __restrict__ bc) {
    int c = blockIdx.x;   // 0..31
    int t = threadIdx.x;  // 0..127
    float acc = 0.f;
#pragma unroll 8
    for (int k = 0; k < HD; k++) acc += W2[t * HD + k] * Wc[k * CD + c];
    g_W2c[t * CD + c] = acc;
    if (t == 0) {
        float a = bc[c];
        for (int k = 0; k < HD; k++) a += b2[k] * Wc[k * CD + c];
        g_bc2[c] = a;
    }
    if (c == 0) {
        if (t < CD) g_msum[t] = 0.f;
        g_hsum[t] = 0.f;
        if (t == 0) { g_barA = 0u; g_barB = 0u; }
    }
}

// ---- software grid barrier (all NB blocks resident) ----
__device__ __forceinline__ void grid_barrier(unsigned* ctr) {
    __syncthreads();
    if (threadIdx.x == 0) {
        __threadfence();
        atomicAdd(ctr, 1u);
        while (*(volatile unsigned*)ctr < (unsigned)NB) {}
    }
    __syncthreads();
}

// ============ FUSED: k1 + k3 + k4 + k5 ============
__global__ void __launch_bounds__(NT, 1) kfused(
    const float* __restrict__ states, const float* __restrict__ noise,
    const float* __restrict__ W1, const float* __restrict__ b1,
    const float* __restrict__ W2, const float* __restrict__ b2,
    const float* __restrict__ Wg, const float* __restrict__ bg,
    const float* __restrict__ Wp, const float* __restrict__ bp,
    const float* __restrict__ Wv, const float* __restrict__ bv,
    const float* __restrict__ Wr, const float* __restrict__ br,
    float* __restrict__ outH, float* __restrict__ outA,
    float* __restrict__ outV, float* __restrict__ outR) {

    extern __shared__ float sm[];
    float* s_s   = sm;                    // ROWS*SD   = 4096
    float* s_w1  = s_s   + ROWS * SD;     // SD*HD     = 8192
    float* s_w1b = s_w1  + SD * HD;       // CD*HD     = 4096 (W1 comm rows)
    float* s_w2c = s_w1b + CD * HD;       // HD*CD     = 4096
    float* s_h   = s_w2c + HD * CD;       // ROWS*HD   = 8192
    float* s_msg = s_h   + ROWS * HD;     // ROWS*33   = 2112
    float* s_rn  = s_msg + ROWS * 33;     // 64
    float* s_bc2 = s_rn  + ROWS;          // 32
    float* s_mh  = s_bc2 + CD;            // 128
    float* s_h2  = s_mh  + HD;            // 128
    float* s_g   = s_h2  + HD;            // 128
    float* s_prt = s_g   + HD;            // 8*128 = 1024
    float* s_hw  = s_prt + 8 * HD;        // 1536

    int t = threadIdx.x;
    int r0 = blockIdx.x * ROWS;

    // ---- stage shared inputs ----
    for (int i = t; i < ROWS * SD; i += NT) s_s[i] = states[r0 * SD + i];
    for (int i = t; i < SD * HD; i += NT) s_w1[i] = W1[i];
    for (int i = t; i < CD * HD; i += NT) s_w1b[i] = W1[SD * HD + i];
    for (int i = t; i < HD * CD; i += NT) s_w2c[i] = g_W2c[i];
    if (t < CD) s_bc2[t] = g_bc2[t];
    for (int i = t; i < HD * 12; i += NT) {
        int k = i / 12, j = i % 12;
        float v;
        if (j < 8)       v = Wp[k * AD + j];
        else if (j == 8) v = Wv[k];
        else             v = Wr[k * 3 + (j - 9)];
        s_hw[i] = v;
    }
    __syncthreads();

    // ---- phase 1: P = states @ W1[:SD] (held in registers) ----
    int c = t & 127;              // output column
    int grp = t >> 7;             // 0..7
    int rb = grp * RPT;           // row base
    float bb = b1[c];
    float acc[RPT];
#pragma unroll
    for (int r = 0; r < RPT; r++) acc[r] = 0.f;

#pragma unroll 4
    for (int k = 0; k < SD; k += 4) {
        float w0 = s_w1[(k + 0) * HD + c];
        float w1v = s_w1[(k + 1) * HD + c];
        float w2v = s_w1[(k + 2) * HD + c];
        float w3v = s_w1[(k + 3) * HD + c];
#pragma unroll
        for (int r = 0; r < RPT; r++) {
            float4 sv = *(const float4*)&s_s[(rb + r) * SD + k];
            acc[r] += sv.x * w0 + sv.y * w1v + sv.z * w2v + sv.w * w3v;
        }
    }
#pragma unroll
    for (int r = 0; r < RPT; r++)
        s_h[(rb + r) * HD + c] = fmaxf(acc[r] + bb, 0.f);
    __syncthreads();

    // ---- phase 2: msgs = l2norm(relu(P+b1) @ W2c + bc2); accumulate msum ----
    {
        int mc = t & 31;          // msg column
        int rg = t >> 5;          // 0..31, 2 rows each
        float m0 = s_bc2[mc], m1 = m0;
#pragma unroll 4
        for (int k = 0; k < HD; k += 4) {
            float w0 = s_w2c[(k + 0) * CD + mc];
            float w1v = s_w2c[(k + 1) * CD + mc];
            float w2v = s_w2c[(k + 2) * CD + mc];
            float w3v = s_w2c[(k + 3) * CD + mc];
            float4 ha = *(const float4*)&s_h[(rg * 2 + 0) * HD + k];
            float4 hb = *(const float4*)&s_h[(rg * 2 + 1) * HD + k];
            m0 += ha.x * w0 + ha.y * w1v + ha.z * w2v + ha.w * w3v;
            m1 += hb.x * w0 + hb.y * w1v + hb.z * w2v + hb.w * w3v;
        }
        s_msg[(rg * 2 + 0) * 33 + mc] = m0;
        s_msg[(rg * 2 + 1) * 33 + mc] = m1;
    }
    __syncthreads();
    if (t < ROWS) {
        float ss = 0.f;
#pragma unroll
        for (int j = 0; j < CD; j++) { float v = s_msg[t * 33 + j]; ss += v * v; }
        s_rn[t] = 1.f / fmaxf(sqrtf(ss), 1e-12f);
    }
    __syncthreads();
    if (t < CD) {
        float p = 0.f;
#pragma unroll
        for (int r = 0; r < ROWS; r++) p += s_msg[r * 33 + t] * s_rn[r];
        atomicAdd(&g_msum[t], p);
    }

    grid_barrier(&g_barA);

    // ---- phase 3: hsum[c] += sum_r relu(acc[r] + bias_eff[c]) ----
    if (t < CD) s_bc2[t] = *(volatile float*)&g_msum[t];  // reuse s_bc2
    __syncthreads();
    {
        float be = bb;
#pragma unroll
        for (int j = 0; j < CD; j++)
            be += (s_bc2[j] * (1.0f / NA)) * s_w1b[j * HD + c];
        float hp = 0.f;
#pragma unroll
        for (int r = 0; r < RPT; r++) hp += fmaxf(acc[r] + be, 0.f);
        s_prt[grp * HD + c] = hp;   // no atomics: 8 partial slabs
    }
    __syncthreads();
    if (t < HD) {
        float v = 0.f;
#pragma unroll
        for (int p = 0; p < 8; p++) v += s_prt[p * HD + t];
        atomicAdd(&g_hsum[t], v);
    }

    grid_barrier(&g_barB);

    // ---- phase 4: g = relu((mean_h @ W2 + b2) @ Wg + bg), redundant/block ----
    if (t < HD) s_mh[t] = *(volatile float*)&g_hsum[t] * (1.0f / NA);
    __syncthreads();
    {
        float w2r[16];
#pragma unroll
        for (int i = 0; i < 16; i++) w2r[i] = W2[(grp * 16 + i) * HD + c];
        float a = 0.f;
#pragma unroll
        for (int i = 0; i < 16; i++) a += s_mh[grp * 16 + i] * w2r[i];
        s_prt[grp * HD + c] = a;
        __syncthreads();
        if (t < HD) {
            float v = b2[t];
#pragma unroll
            for (int p = 0; p < 8; p++) v += s_prt[p * HD + t];
            s_h2[t] = v;
        }
        __syncthreads();
        float wgr[16];
#pragma unroll
        for (int i = 0; i < 16; i++) wgr[i] = Wg[(grp * 16 + i) * HD + c];
        float g2 = 0.f;
#pragma unroll
        for (int i = 0; i < 16; i++) g2 += s_h2[grp * 16 + i] * wgr[i];
        s_prt[grp * HD + c] = g2;
        __syncthreads();
        if (t < HD) {
            float v = bg[t];
#pragma unroll
            for (int p = 0; p < 8; p++) v += s_prt[p * HD + t];
            s_g[t] = fmaxf(v, 0.f);
        }
        __syncthreads();
    }

    // ---- phase 5: H = l2norm(g + 0.01*noise); heads. 2 rows per warp ----
    {
        int w = t >> 5, lane = t & 31;
        int rowb = r0 + w * 2;
        const float* nb = noise + (size_t)rowb * HD;
        float gp0 = s_g[lane +  0], gp1 = s_g[lane + 32];
        float gp2 = s_g[lane + 64], gp3 = s_g[lane + 96];
        float bpv = (lane < 8) ? bp[lane] : 0.f;
        float bvv = bv[0];
        float br0 = br[0], br1 = br[1], br2 = br[2];

        // front-batch all 8 noise loads (one DRAM round trip per warp)
        float nz[2][4];
#pragma unroll
        for (int i = 0; i < 2; i++) {
            nz[i][0] = nb[i * HD + lane +  0];
            nz[i][1] = nb[i * HD + lane + 32];
            nz[i][2] = nb[i * HD + lane + 64];
            nz[i][3] = nb[i * HD + lane + 96];
        }

#pragma unroll
        for (int i = 0; i < 2; i++) {
            int row = rowb + i;
            float v0 = gp0 + 0.01f * nz[i][0];
            float v1 = gp1 + 0.01f * nz[i][1];
            float v2 = gp2 + 0.01f * nz[i][2];
            float v3 = gp3 + 0.01f * nz[i][3];
            float ss = v0 * v0 + v1 * v1 + v2 * v2 + v3 * v3;
#pragma unroll
            for (int o = 16; o; o >>= 1) ss += __shfl_xor_sync(0xffffffffu, ss, o);
            float rn = 1.f / fmaxf(sqrtf(ss), 1e-12f);
            float h[4] = {v0 * rn, v1 * rn, v2 * rn, v3 * rn};

            float* oh = outH + (size_t)row * HD;
            oh[lane +  0] = h[0];
            oh[lane + 32] = h[1];
            oh[lane + 64] = h[2];
            oh[lane + 96] = h[3];

            float hd_[12];
#pragma unroll
            for (int j = 0; j < 12; j++) hd_[j] = 0.f;
#pragma unroll
            for (int m = 0; m < 4; m++) {
                int k = lane + 32 * m;
                const float4* wrow = (const float4*)&s_hw[k * 12];
                float4 wa = wrow[0], wb2 = wrow[1], wc2 = wrow[2];
                float hv = h[m];
                hd_[0] += hv * wa.x;  hd_[1] += hv * wa.y;
                hd_[2] += hv * wa.z;  hd_[3] += hv * wa.w;
                hd_[4] += hv * wb2.x; hd_[5] += hv * wb2.y;
                hd_[6] += hv * wb2.z; hd_[7] += hv * wb2.w;
                hd_[8] += hv * wc2.x; hd_[9] += hv * wc2.y;
                hd_[10] += hv * wc2.z; hd_[11] += hv * wc2.w;
            }
#pragma unroll
            for (int j = 0; j < 12; j++) {
#pragma unroll
                for (int o = 16; o; o >>= 1)
                    hd_[j] += __shfl_xor_sync(0xffffffffu, hd_[j], o);
            }

            if (lane < 8) {
                outA[(size_t)row * AD + lane] = tanhf(hd_[lane] + bpv);
            } else if (lane == 8) {
                outV[row] = hd_[8] + bvv;
            } else if (lane == 9) {
                float z0 = hd_[9] + br0, z1 = hd_[10] + br1, z2 = hd_[11] + br2;
                float mx = fmaxf(z0, fmaxf(z1, z2));
                float e0 = expf(z0 - mx), e1 = expf(z1 - mx), e2 = expf(z2 - mx);
                float inv = 1.f / (e0 + e1 + e2);
                outR[(size_t)row * 3 + 0] = e0 * inv;
                outR[(size_t)row * 3 + 1] = e1 * inv;
                outR[(size_t)row * 3 + 2] = e2 * inv;
            }
        }
    }
}

#define FUSED_SMEM ((ROWS*SD + SD*HD + CD*HD + HD*CD + ROWS*HD + ROWS*33 + \
                     ROWS + CD + HD + HD + HD + 8*HD + HD*12) * 4)

extern "C" void kernel_launch(void* const* d_in, const int* in_sizes, int n_in,
                              void* d_out, int out_size) {
    const float* states = (const float*)d_in[0];
    const float* noise  = (const float*)d_in[1];
    const float* W1 = (const float*)d_in[2];
    const float* b1 = (const float*)d_in[3];
    const float* W2 = (const float*)d_in[4];
    const float* b2 = (const float*)d_in[5];
    const float* Wc = (const float*)d_in[6];
    const float* bc = (const float*)d_in[7];
    const float* Wg = (const float*)d_in[8];
    const float* bg = (const float*)d_in[9];
    const float* Wp = (const float*)d_in[10];
    const float* bp = (const float*)d_in[11];
    const float* Wv = (const float*)d_in[12];
    const float* bv = (const float*)d_in[13];
    const float* Wr = (const float*)d_in[14];
    const float* br = (const float*)d_in[15];

    float* outH = (float*)d_out;                       // [N, HD]
    float* outA = outH + (size_t)NA * HD;              // [N, AD]
    float* outV = outA + (size_t)NA * AD;              // [N, 1]
    float* outR = outV + (size_t)NA;                   // [N, 3]

    cudaFuncSetAttribute(kfused, cudaFuncAttributeMaxDynamicSharedMemorySize,
                         FUSED_SMEM);

    k0<<<CD, 128>>>(W2, Wc, b2, bc);
    kfused<<<NB, NT, FUSED_SMEM>>>(states, noise, W1, b1, W2, b2, Wg, bg,
                                   Wp, bp, Wv, bv, Wr, br,
                                   outH, outA, outV, outR);
}

// round 6
// speedup vs baseline: 1.0044x; 1.0044x over previous
#include <cuda_runtime.h>
#include <math.h>

#define NA 8192
#define SD 64
#define HD 128
#define CD 32
#define AD 8
#define NB 256      // 2 CTAs/SM on 148 SMs -> all resident, grid barrier safe
#define NT 512
#define ROWS 32     // rows per block
#define RPT 8       // rows per thread in phases 1/3 (4 column-groups of 128)
#define NGRP 4

// -------- device scratch --------
__device__ float g_W2c[HD * CD];    // W2 @ Wc
__device__ float g_bc2[CD];         // b2 @ Wc + bc
__device__ float g_msum[CD];        // sum of normalized msgs
__device__ float g_hsum[HD];        // column sum of relu(P + bias_eff)
__device__ unsigned g_barA, g_barB; // grid barrier counters (reset by k0)

// ============ K0: fold W2c, bc2; zero accumulators + barriers. 32 x 128 ======
__global__ void k0(const float* __restrict__ W2, const float* __restrict__ Wc,
                   const float* __restrict__ b2, const float* __restrict__ bc) {
    int c = blockIdx.x;   // 0..31
    int t = threadIdx.x;  // 0..127
    float acc = 0.f;
#pragma unroll 8
    for (int k = 0; k < HD; k++) acc += W2[t * HD + k] * Wc[k * CD + c];
    g_W2c[t * CD + c] = acc;
    if (t == 0) {
        float a = bc[c];
        for (int k = 0; k < HD; k++) a += b2[k] * Wc[k * CD + c];
        g_bc2[c] = a;
    }
    if (c == 0) {
        if (t < CD) g_msum[t] = 0.f;
        g_hsum[t] = 0.f;
        if (t == 0) { g_barA = 0u; g_barB = 0u; }
    }
}

// ---- software grid barrier (all NB blocks resident) ----
__device__ __forceinline__ void grid_barrier(unsigned* ctr) {
    __syncthreads();
    if (threadIdx.x == 0) {
        __threadfence();
        atomicAdd(ctr, 1u);
        while (*(volatile unsigned*)ctr < (unsigned)NB) {}
    }
    __syncthreads();
}

// ============ FUSED: k1 + k3 + k4 + k5 ============
__global__ void __launch_bounds__(NT, 2) kfused(
    const float* __restrict__ states, const float* __restrict__ noise,
    const float* __restrict__ W1, const float* __restrict__ b1,
    const float* __restrict__ W2, const float* __restrict__ b2,
    const float* __restrict__ Wg, const float* __restrict__ bg,
    const float* __restrict__ Wp, const float* __restrict__ bp,
    const float* __restrict__ Wv, const float* __restrict__ bv,
    const float* __restrict__ Wr, const float* __restrict__ br,
    float* __restrict__ outH, float* __restrict__ outA,
    float* __restrict__ outV, float* __restrict__ outR) {

    extern __shared__ float sm[];
    float* s_s   = sm;                    // ROWS*SD   = 2048
    float* s_w2c = s_s   + ROWS * SD;     // HD*CD     = 4096
    float* s_h   = s_w2c + HD * CD;       // ROWS*HD   = 4096
    float* s_msg = s_h   + ROWS * HD;     // ROWS*33   = 1056
    float* s_rn  = s_msg + ROWS * 33;     // 32
    float* s_bc2 = s_rn  + ROWS;          // 32
    float* s_mh  = s_bc2 + CD;            // 128
    float* s_h2  = s_mh  + HD;            // 128
    float* s_g   = s_h2  + HD;            // 128
    float* s_prt = s_g   + HD;            // NGRP*128 = 512
    float* s_hw  = s_prt + NGRP * HD;     // 1536

    int t = threadIdx.x;
    int r0 = blockIdx.x * ROWS;

    // ---- stage shared inputs ----
    for (int i = t; i < ROWS * SD; i += NT) s_s[i] = states[r0 * SD + i];
    for (int i = t; i < HD * CD; i += NT) s_w2c[i] = g_W2c[i];
    if (t < CD) s_bc2[t] = g_bc2[t];
    for (int i = t; i < HD * 12; i += NT) {
        int k = i / 12, j = i % 12;
        float v;
        if (j < 8)       v = Wp[k * AD + j];
        else if (j == 8) v = Wv[k];
        else             v = Wr[k * 3 + (j - 9)];
        s_hw[i] = v;
    }
    __syncthreads();

    // ---- phase 1: P = states @ W1[:SD] (held in registers) ----
    int c = t & 127;              // output column
    int grp = t >> 7;             // 0..3
    int rb = grp * RPT;           // row base
    float bb = b1[c];
    float acc[RPT];
#pragma unroll
    for (int r = 0; r < RPT; r++) acc[r] = 0.f;

#pragma unroll 4
    for (int k = 0; k < SD; k += 4) {
        float w0 = __ldg(&W1[(k + 0) * HD + c]);   // L1-resident after first pass
        float w1v = __ldg(&W1[(k + 1) * HD + c]);
        float w2v = __ldg(&W1[(k + 2) * HD + c]);
        float w3v = __ldg(&W1[(k + 3) * HD + c]);
#pragma unroll
        for (int r = 0; r < RPT; r++) {
            float4 sv = *(const float4*)&s_s[(rb + r) * SD + k];
            acc[r] += sv.x * w0 + sv.y * w1v + sv.z * w2v + sv.w * w3v;
        }
    }
#pragma unroll
    for (int r = 0; r < RPT; r++)
        s_h[(rb + r) * HD + c] = fmaxf(acc[r] + bb, 0.f);
    __syncthreads();

    // ---- phase 2: msgs = l2norm(relu(P+b1) @ W2c + bc2); accumulate msum ----
    {
        int mc = t & 31;          // msg column
        int rg = t >> 5;          // 0..15, 2 rows each
        float m0 = s_bc2[mc], m1 = m0;
#pragma unroll 4
        for (int k = 0; k < HD; k += 4) {
            float w0 = s_w2c[(k + 0) * CD + mc];
            float w1v = s_w2c[(k + 1) * CD + mc];
            float w2v = s_w2c[(k + 2) * CD + mc];
            float w3v = s_w2c[(k + 3) * CD + mc];
            float4 ha = *(const float4*)&s_h[(rg * 2 + 0) * HD + k];
            float4 hb = *(const float4*)&s_h[(rg * 2 + 1) * HD + k];
            m0 += ha.x * w0 + ha.y * w1v + ha.z * w2v + ha.w * w3v;
            m1 += hb.x * w0 + hb.y * w1v + hb.z * w2v + hb.w * w3v;
        }
        s_msg[(rg * 2 + 0) * 33 + mc] = m0;
        s_msg[(rg * 2 + 1) * 33 + mc] = m1;
    }
    __syncthreads();
    if (t < ROWS) {
        float ss = 0.f;
#pragma unroll
        for (int j = 0; j < CD; j++) { float v = s_msg[t * 33 + j]; ss += v * v; }
        s_rn[t] = 1.f / fmaxf(sqrtf(ss), 1e-12f);
    }
    __syncthreads();
    if (t < CD) {
        float p = 0.f;
#pragma unroll
        for (int r = 0; r < ROWS; r++) p += s_msg[r * 33 + t] * s_rn[r];
        atomicAdd(&g_msum[t], p);
    }

    grid_barrier(&g_barA);

    // ---- phase 3: hsum[c] += sum_r relu(acc[r] + bias_eff[c]) ----
    if (t < CD) s_bc2[t] = *(volatile float*)&g_msum[t];  // reuse s_bc2
    __syncthreads();
    {
        float be = bb;
#pragma unroll
        for (int j = 0; j < CD; j++)
            be += (s_bc2[j] * (1.0f / NA)) * __ldg(&W1[(SD + j) * HD + c]);
        float hp = 0.f;
#pragma unroll
        for (int r = 0; r < RPT; r++) hp += fmaxf(acc[r] + be, 0.f);
        s_prt[grp * HD + c] = hp;   // no atomics: NGRP partial slabs
    }
    __syncthreads();
    if (t < HD) {
        float v = 0.f;
#pragma unroll
        for (int p = 0; p < NGRP; p++) v += s_prt[p * HD + t];
        atomicAdd(&g_hsum[t], v);
    }

    grid_barrier(&g_barB);

    // ---- phase 4: g = relu((mean_h @ W2 + b2) @ Wg + bg), redundant/block ----
    if (t < HD) s_mh[t] = *(volatile float*)&g_hsum[t] * (1.0f / NA);
    __syncthreads();
    {
        // each grp covers 32 k, in two front-batched chunks of 16
        float a = 0.f;
#pragma unroll
        for (int hseg = 0; hseg < 2; hseg++) {
            int kb = grp * 32 + hseg * 16;
            float w2r[16];
#pragma unroll
            for (int i = 0; i < 16; i++) w2r[i] = W2[(kb + i) * HD + c];
#pragma unroll
            for (int i = 0; i < 16; i++) a += s_mh[kb + i] * w2r[i];
        }
        s_prt[grp * HD + c] = a;
        __syncthreads();
        if (t < HD) {
            float v = b2[t];
#pragma unroll
            for (int p = 0; p < NGRP; p++) v += s_prt[p * HD + t];
            s_h2[t] = v;
        }
        __syncthreads();
        float g2 = 0.f;
#pragma unroll
        for (int hseg = 0; hseg < 2; hseg++) {
            int kb = grp * 32 + hseg * 16;
            float wgr[16];
#pragma unroll
            for (int i = 0; i < 16; i++) wgr[i] = Wg[(kb + i) * HD + c];
#pragma unroll
            for (int i = 0; i < 16; i++) g2 += s_h2[kb + i] * wgr[i];
        }
        s_prt[grp * HD + c] = g2;
        __syncthreads();
        if (t < HD) {
            float v = bg[t];
#pragma unroll
            for (int p = 0; p < NGRP; p++) v += s_prt[p * HD + t];
            s_g[t] = fmaxf(v, 0.f);
        }
        __syncthreads();
    }

    // ---- phase 5: H = l2norm(g + 0.01*noise); heads. 2 rows per warp ----
    {
        int w = t >> 5, lane = t & 31;
        int rowb = r0 + w * 2;
        const float* nb = noise + (size_t)rowb * HD;
        float gp0 = s_g[lane +  0], gp1 = s_g[lane + 32];
        float gp2 = s_g[lane + 64], gp3 = s_g[lane + 96];
        float bpv = (lane < 8) ? bp[lane] : 0.f;
        float bvv = bv[0];
        float br0 = br[0], br1 = br[1], br2 = br[2];

        // front-batch all 8 noise loads (one DRAM round trip per warp)
        float nz[2][4];
#pragma unroll
        for (int i = 0; i < 2; i++) {
            nz[i][0] = nb[i * HD + lane +  0];
            nz[i][1] = nb[i * HD + lane + 32];
            nz[i][2] = nb[i * HD + lane + 64];
            nz[i][3] = nb[i * HD + lane + 96];
        }

#pragma unroll
        for (int i = 0; i < 2; i++) {
            int row = rowb + i;
            float v0 = gp0 + 0.01f * nz[i][0];
            float v1 = gp1 + 0.01f * nz[i][1];
            float v2 = gp2 + 0.01f * nz[i][2];
            float v3 = gp3 + 0.01f * nz[i][3];
            float ss = v0 * v0 + v1 * v1 + v2 * v2 + v3 * v3;
#pragma unroll
            for (int o = 16; o; o >>= 1) ss += __shfl_xor_sync(0xffffffffu, ss, o);
            float rn = 1.f / fmaxf(sqrtf(ss), 1e-12f);
            float h[4] = {v0 * rn, v1 * rn, v2 * rn, v3 * rn};

            float* oh = outH + (size_t)row * HD;
            oh[lane +  0] = h[0];
            oh[lane + 32] = h[1];
            oh[lane + 64] = h[2];
            oh[lane + 96] = h[3];

            float hd_[12];
#pragma unroll
            for (int j = 0; j < 12; j++) hd_[j] = 0.f;
#pragma unroll
            for (int m = 0; m < 4; m++) {
                int k = lane + 32 * m;
                const float4* wrow = (const float4*)&s_hw[k * 12];
                float4 wa = wrow[0], wb2 = wrow[1], wc2 = wrow[2];
                float hv = h[m];
                hd_[0] += hv * wa.x;  hd_[1] += hv * wa.y;
                hd_[2] += hv * wa.z;  hd_[3] += hv * wa.w;
                hd_[4] += hv * wb2.x; hd_[5] += hv * wb2.y;
                hd_[6] += hv * wb2.z; hd_[7] += hv * wb2.w;
                hd_[8] += hv * wc2.x; hd_[9] += hv * wc2.y;
                hd_[10] += hv * wc2.z; hd_[11] += hv * wc2.w;
            }
#pragma unroll
            for (int j = 0; j < 12; j++) {
#pragma unroll
                for (int o = 16; o; o >>= 1)
                    hd_[j] += __shfl_xor_sync(0xffffffffu, hd_[j], o);
            }

            if (lane < 8) {
                outA[(size_t)row * AD + lane] = tanhf(hd_[lane] + bpv);
            } else if (lane == 8) {
                outV[row] = hd_[8] + bvv;
            } else if (lane == 9) {
                float z0 = hd_[9] + br0, z1 = hd_[10] + br1, z2 = hd_[11] + br2;
                float mx = fmaxf(z0, fmaxf(z1, z2));
                float e0 = expf(z0 - mx), e1 = expf(z1 - mx), e2 = expf(z2 - mx);
                float inv = 1.f / (e0 + e1 + e2);
                outR[(size_t)row * 3 + 0] = e0 * inv;
                outR[(size_t)row * 3 + 1] = e1 * inv;
                outR[(size_t)row * 3 + 2] = e2 * inv;
            }
        }
    }
}

#define FUSED_SMEM ((ROWS*SD + HD*CD + ROWS*HD + ROWS*33 + ROWS + CD + \
                     HD + HD + HD + NGRP*HD + HD*12) * 4)

extern "C" void kernel_launch(void* const* d_in, const int* in_sizes, int n_in,
                              void* d_out, int out_size) {
    const float* states = (const float*)d_in[0];
    const float* noise  = (const float*)d_in[1];
    const float* W1 = (const float*)d_in[2];
    const float* b1 = (const float*)d_in[3];
    const float* W2 = (const float*)d_in[4];
    const float* b2 = (const float*)d_in[5];
    const float* Wc = (const float*)d_in[6];
    const float* bc = (const float*)d_in[7];
    const float* Wg = (const float*)d_in[8];
    const float* bg = (const float*)d_in[9];
    const float* Wp = (const float*)d_in[10];
    const float* bp = (const float*)d_in[11];
    const float* Wv = (const float*)d_in[12];
    const float* bv = (const float*)d_in[13];
    const float* Wr = (const float*)d_in[14];
    const float* br = (const float*)d_in[15];

    float* outH = (float*)d_out;                       // [N, HD]
    float* outA = outH + (size_t)NA * HD;              // [N, AD]
    float* outV = outA + (size_t)NA * AD;              // [N, 1]
    float* outR = outV + (size_t)NA;                   // [N, 3]

    cudaFuncSetAttribute(kfused, cudaFuncAttributeMaxDynamicSharedMemorySize,
                         FUSED_SMEM);

    k0<<<CD, 128>>>(W2, Wc, b2, bc);
    kfused<<<NB, NT, FUSED_SMEM>>>(states, noise, W1, b1, W2, b2, Wg, bg,
                                   Wp, bp, Wv, bv, Wr, br,
                                   outH, outA, outV, outR);
}

// round 7
// speedup vs baseline: 1.3047x; 1.2989x over previous
#include <cuda_runtime.h>
#include <math.h>

#define NA 8192
#define SD 64
#define HD 128
#define CD 32
#define AD 8
#define NB 128
#define NT 1024
#define ROWS 64

// -------- device scratch (zero-initialized; kernel self-resets) --------
__device__ float g_W2cT[CD * HD];   // (W2@Wc)^T : [c][k]
__device__ float g_bc2[CD];         // b2@Wc + bc
__device__ float g_msum[CD];
__device__ float g_hsum[HD];
__device__ unsigned g_barW, g_barA, g_barB, g_done;

__device__ __forceinline__ void grid_barrier(unsigned* ctr) {
    __syncthreads();
    if (threadIdx.x == 0) {
        __threadfence();
        atomicAdd(ctr, 1u);
        while (*(volatile unsigned*)ctr < (unsigned)NB) {}
    }
    __syncthreads();
}

__global__ void __launch_bounds__(NT, 1) kfused(
    const float* __restrict__ states, const float* __restrict__ noise,
    const float* __restrict__ W1, const float* __restrict__ b1,
    const float* __restrict__ W2, const float* __restrict__ b2,
    const float* __restrict__ Wc, const float* __restrict__ bc,
    const float* __restrict__ Wg, const float* __restrict__ bg,
    const float* __restrict__ Wp, const float* __restrict__ bp,
    const float* __restrict__ Wv, const float* __restrict__ bv,
    const float* __restrict__ Wr, const float* __restrict__ br,
    float* __restrict__ outH, float* __restrict__ outA,
    float* __restrict__ outV, float* __restrict__ outR) {

    extern __shared__ float sm[];
    float* s_s    = sm;               // 4096: states[64][64]; later W1comm[32][128]
    float* s_wh   = s_s + 4096;       // 8192: W1[0:64][128]; later h[64][128]
    float* s_w2cT = s_wh + 8192;      // 32*132 = 4224 (padded transpose)
    float* s_msg  = s_w2cT + 4224;    // 64*33 = 2112
    float* s_rn   = s_msg + 2112;     // 64
    float* s_ms   = s_rn + 64;        // 32
    float* s_bc2  = s_ms + 32;        // 32
    float* s_mh   = s_bc2 + 32;       // 128
    float* s_h2   = s_mh + 128;       // 128
    float* s_g    = s_h2 + 128;       // 128
    float* s_prt  = s_g + 128;        // 16*128 = 2048
    float* s_hw   = s_prt + 2048;     // 1536

    int t = threadIdx.x;
    int bid = blockIdx.x;
    int r0 = bid * ROWS;

    // ---- stage: states, W1[0:64], head weights ----
    ((float4*)s_s)[t] = ((const float4*)(states + (size_t)r0 * SD))[t];
    ((float4*)s_wh)[t] = ((const float4*)W1)[t];
    ((float4*)s_wh)[t + 1024] = ((const float4*)W1)[t + 1024];
    for (int i = t; i < HD * 12; i += NT) {
        int k = i / 12, j = i % 12;
        float v;
        if (j < 8)       v = Wp[k * AD + j];
        else if (j == 8) v = Wv[k];
        else             v = Wr[k * 3 + (j - 9)];
        s_hw[i] = v;
    }

    // ---- distributed W2c^T: this CTA's 32 elements (one per warp) ----
    {
        int w = t >> 5, l = t & 31;
        int idx = bid * 32 + w;           // 0..4095
        int c = idx & 31, k = idx >> 5;   // c 0..31, k 0..127
        float4 w2v = *(const float4*)&W2[k * HD + l * 4];
        float d = w2v.x * Wc[(l * 4 + 0) * CD + c] +
                  w2v.y * Wc[(l * 4 + 1) * CD + c] +
                  w2v.z * Wc[(l * 4 + 2) * CD + c] +
                  w2v.w * Wc[(l * 4 + 3) * CD + c];
#pragma unroll
        for (int o = 16; o; o >>= 1) d += __shfl_xor_sync(0xffffffffu, d, o);
        if (l == 0) g_W2cT[c * HD + k] = d;
        if (bid == 1) {   // bc2 (32 dots) computed by CTA 1's warps
            float4 b2v = *(const float4*)&b2[l * 4];
            float e = b2v.x * Wc[(l * 4 + 0) * CD + w] +
                      b2v.y * Wc[(l * 4 + 1) * CD + w] +
                      b2v.z * Wc[(l * 4 + 2) * CD + w] +
                      b2v.w * Wc[(l * 4 + 3) * CD + w];
#pragma unroll
            for (int o = 16; o; o >>= 1) e += __shfl_xor_sync(0xffffffffu, e, o);
            if (l == 0) g_bc2[w] = e + bc[w];
        }
    }
    __syncthreads();

    // ---- phase 1: P = states @ W1[:64]; tile 4 rows x 2 cols per thread ----
    int c0 = (t & 63) * 2;
    int rg1 = t >> 6;          // 0..15
    int rb = rg1 * 4;
    float2 b1v = *(const float2*)&b1[c0];
    float a0[4], a1[4];
#pragma unroll
    for (int r = 0; r < 4; r++) { a0[r] = 0.f; a1[r] = 0.f; }

#pragma unroll 4
    for (int k = 0; k < SD; k += 4) {
        float2 w0 = *(const float2*)&s_wh[(k + 0) * HD + c0];
        float2 w1v = *(const float2*)&s_wh[(k + 1) * HD + c0];
        float2 w2v = *(const float2*)&s_wh[(k + 2) * HD + c0];
        float2 w3v = *(const float2*)&s_wh[(k + 3) * HD + c0];
#pragma unroll
        for (int r = 0; r < 4; r++) {
            float4 sv = *(const float4*)&s_s[(rb + r) * SD + k];
            a0[r] += sv.x * w0.x + sv.y * w1v.x + sv.z * w2v.x + sv.w * w3v.x;
            a1[r] += sv.x * w0.y + sv.y * w1v.y + sv.z * w2v.y + sv.w * w3v.y;
        }
    }
    __syncthreads();   // all reads of s_wh (W1) and s_s (states) done

    // h = relu(P + b1) into s_wh region; stage W1 comm rows into s_s
#pragma unroll
    for (int r = 0; r < 4; r++) {
        float2 hv = { fmaxf(a0[r] + b1v.x, 0.f), fmaxf(a1[r] + b1v.y, 0.f) };
        *(float2*)&s_wh[(rb + r) * HD + c0] = hv;
    }
    ((float4*)s_s)[t] = ((const float4*)(W1 + SD * HD))[t];   // 32x128 comm rows

    grid_barrier(&g_barW);   // publishes W2cT/bc2 globally; local stores synced

    // stage W2c^T (padded) + bc2
    {
        int c = t & 31, kg = t >> 5;    // kg 0..31
        *(float4*)&s_w2cT[c * 132 + kg * 4] =
            *(const float4*)&g_W2cT[c * HD + kg * 4];
    }
    if (t < CD) s_bc2[t] = *(volatile float*)&g_bc2[t];
    __syncthreads();

    // ---- phase 2: msgs = l2norm(h @ W2c + bc2); accumulate msum ----
    {
        int mc = t & 31, rg = t >> 5;   // rg 0..31 -> rows 2rg, 2rg+1
        float m0 = s_bc2[mc], m1 = m0;
#pragma unroll 4
        for (int k = 0; k < HD; k += 4) {
            float4 wv = *(const float4*)&s_w2cT[mc * 132 + k];
            float4 h0 = *(const float4*)&s_wh[(2 * rg + 0) * HD + k];
            float4 h1 = *(const float4*)&s_wh[(2 * rg + 1) * HD + k];
            m0 += h0.x * wv.x + h0.y * wv.y + h0.z * wv.z + h0.w * wv.w;
            m1 += h1.x * wv.x + h1.y * wv.y + h1.z * wv.z + h1.w * wv.w;
        }
        s_msg[(2 * rg + 0) * 33 + mc] = m0;
        s_msg[(2 * rg + 1) * 33 + mc] = m1;
    }
    __syncthreads();
    if (t < ROWS) {
        float ss = 0.f;
#pragma unroll
        for (int j = 0; j < CD; j++) { float v = s_msg[t * 33 + j]; ss += v * v; }
        s_rn[t] = 1.f / fmaxf(sqrtf(ss), 1e-12f);
    }
    __syncthreads();
    if (t < CD) {
        float p = 0.f;
#pragma unroll
        for (int r = 0; r < ROWS; r++) p += s_msg[r * 33 + t] * s_rn[r];
        atomicAdd(&g_msum[t], p);
    }

    grid_barrier(&g_barA);

    // ---- phase 3: hsum[c] += sum_r relu(P + bias_eff) ----
    if (t < CD) s_ms[t] = *(volatile float*)&g_msum[t];
    __syncthreads();
    {
        float be0 = b1v.x, be1 = b1v.y;
#pragma unroll
        for (int j = 0; j < CD; j++) {
            float mj = s_ms[j] * (1.0f / NA);
            float2 wv = *(const float2*)&s_s[j * HD + c0];   // W1 comm rows
            be0 += mj * wv.x;
            be1 += mj * wv.y;
        }
        float hp0 = 0.f, hp1 = 0.f;
#pragma unroll
        for (int r = 0; r < 4; r++) {
            hp0 += fmaxf(a0[r] + be0, 0.f);
            hp1 += fmaxf(a1[r] + be1, 0.f);
        }
        *(float2*)&s_prt[rg1 * HD + c0] = make_float2(hp0, hp1);
    }
    __syncthreads();
    if (t < HD) {
        float v = 0.f;
#pragma unroll
        for (int p = 0; p < 16; p++) v += s_prt[p * HD + t];
        atomicAdd(&g_hsum[t], v);
    }

    grid_barrier(&g_barB);

    // ---- phase 4: g = relu((mean_h @ W2 + b2) @ Wg + bg) ----
    if (t < HD) s_mh[t] = *(volatile float*)&g_hsum[t] * (1.0f / NA);
    __syncthreads();
    {
        int cc = t & 127, grp4 = t >> 7;   // 8 k-groups of 16
        float w2r[16];
#pragma unroll
        for (int i = 0; i < 16; i++) w2r[i] = W2[(grp4 * 16 + i) * HD + cc];
        float a = 0.f;
#pragma unroll
        for (int i = 0; i < 16; i++) a += s_mh[grp4 * 16 + i] * w2r[i];
        s_prt[grp4 * HD + cc] = a;
        __syncthreads();
        if (t < HD) {
            float v = b2[t];
#pragma unroll
            for (int p = 0; p < 8; p++) v += s_prt[p * HD + t];
            s_h2[t] = v;
        }
        __syncthreads();
        float wgr[16];
#pragma unroll
        for (int i = 0; i < 16; i++) wgr[i] = Wg[(grp4 * 16 + i) * HD + cc];
        float g2 = 0.f;
#pragma unroll
        for (int i = 0; i < 16; i++) g2 += s_h2[grp4 * 16 + i] * wgr[i];
        s_prt[grp4 * HD + cc] = g2;
        __syncthreads();
        if (t < HD) {
            float v = bg[t];
#pragma unroll
            for (int p = 0; p < 8; p++) v += s_prt[p * HD + t];
            s_g[t] = fmaxf(v, 0.f);
        }
        __syncthreads();
    }

    // ---- phase 5: H = l2norm(g + 0.01*noise); heads. 2 rows per warp ----
    {
        int w = t >> 5, lane = t & 31;
        int rowb = r0 + w * 2;
        const float* nb = noise + (size_t)rowb * HD;
        float gp0 = s_g[lane +  0], gp1 = s_g[lane + 32];
        float gp2 = s_g[lane + 64], gp3 = s_g[lane + 96];
        float bpv = (lane < 8) ? bp[lane] : 0.f;
        float bvv = bv[0];
        float br0 = br[0], br1 = br[1], br2 = br[2];

        float nz[2][4];
#pragma unroll
        for (int i = 0; i < 2; i++) {
            nz[i][0] = nb[i * HD + lane +  0];
            nz[i][1] = nb[i * HD + lane + 32];
            nz[i][2] = nb[i * HD + lane + 64];
            nz[i][3] = nb[i * HD + lane + 96];
        }

#pragma unroll
        for (int i = 0; i < 2; i++) {
            int row = rowb + i;
            float v0 = gp0 + 0.01f * nz[i][0];
            float v1 = gp1 + 0.01f * nz[i][1];
            float v2 = gp2 + 0.01f * nz[i][2];
            float v3 = gp3 + 0.01f * nz[i][3];
            float ss = v0 * v0 + v1 * v1 + v2 * v2 + v3 * v3;
#pragma unroll
            for (int o = 16; o; o >>= 1) ss += __shfl_xor_sync(0xffffffffu, ss, o);
            float rn = 1.f / fmaxf(sqrtf(ss), 1e-12f);
            float h[4] = {v0 * rn, v1 * rn, v2 * rn, v3 * rn};

            float* oh = outH + (size_t)row * HD;
            oh[lane +  0] = h[0];
            oh[lane + 32] = h[1];
            oh[lane + 64] = h[2];
            oh[lane + 96] = h[3];

            float hd_[12];
#pragma unroll
            for (int j = 0; j < 12; j++) hd_[j] = 0.f;
#pragma unroll
            for (int m = 0; m < 4; m++) {
                int k = lane + 32 * m;
                const float4* wrow = (const float4*)&s_hw[k * 12];
                float4 wa = wrow[0], wb2 = wrow[1], wc2 = wrow[2];
                float hv = h[m];
                hd_[0] += hv * wa.x;  hd_[1] += hv * wa.y;
                hd_[2] += hv * wa.z;  hd_[3] += hv * wa.w;
                hd_[4] += hv * wb2.x; hd_[5] += hv * wb2.y;
                hd_[6] += hv * wb2.z; hd_[7] += hv * wb2.w;
                hd_[8] += hv * wc2.x; hd_[9] += hv * wc2.y;
                hd_[10] += hv * wc2.z; hd_[11] += hv * wc2.w;
            }
#pragma unroll
            for (int j = 0; j < 12; j++) {
#pragma unroll
                for (int o = 16; o; o >>= 1)
                    hd_[j] += __shfl_xor_sync(0xffffffffu, hd_[j], o);
            }

            if (lane < 8) {
                outA[(size_t)row * AD + lane] = tanhf(hd_[lane] + bpv);
            } else if (lane == 8) {
                outV[row] = hd_[8] + bvv;
            } else if (lane == 9) {
                float z0 = hd_[9] + br0, z1 = hd_[10] + br1, z2 = hd_[11] + br2;
                float mx = fmaxf(z0, fmaxf(z1, z2));
                float e0 = expf(z0 - mx), e1 = expf(z1 - mx), e2 = expf(z2 - mx);
                float inv = 1.f / (e0 + e1 + e2);
                outR[(size_t)row * 3 + 0] = e0 * inv;
                outR[(size_t)row * 3 + 1] = e1 * inv;
                outR[(size_t)row * 3 + 2] = e2 * inv;
            }
        }
    }

    // ---- epilogue: last CTA resets global state for next graph replay ----
    __syncthreads();
    if (t == 0) {
        __threadfence();
        unsigned v = atomicAdd(&g_done, 1u);
        if (v == (unsigned)(NB - 1)) {
#pragma unroll
            for (int i = 0; i < CD; i++) g_msum[i] = 0.f;
#pragma unroll
            for (int i = 0; i < HD; i++) g_hsum[i] = 0.f;
            g_barW = 0u; g_barA = 0u; g_barB = 0u;
            __threadfence();
            g_done = 0u;
        }
    }
}

#define FUSED_SMEM ((4096 + 8192 + 4224 + 2112 + 64 + 32 + 32 + 128 + 128 + \
                     128 + 2048 + 1536) * 4)

extern "C" void kernel_launch(void* const* d_in, const int* in_sizes, int n_in,
                              void* d_out, int out_size) {
    const float* states = (const float*)d_in[0];
    const float* noise  = (const float*)d_in[1];
    const float* W1 = (const float*)d_in[2];
    const float* b1 = (const float*)d_in[3];
    const float* W2 = (const float*)d_in[4];
    const float* b2 = (const float*)d_in[5];
    const float* Wc = (const float*)d_in[6];
    const float* bc = (const float*)d_in[7];
    const float* Wg = (const float*)d_in[8];
    const float* bg = (const float*)d_in[9];
    const float* Wp = (const float*)d_in[10];
    const float* bp = (const float*)d_in[11];
    const float* Wv = (const float*)d_in[12];
    const float* bv = (const float*)d_in[13];
    const float* Wr = (const float*)d_in[14];
    const float* br = (const float*)d_in[15];

    float* outH = (float*)d_out;                       // [N, HD]
    float* outA = outH + (size_t)NA * HD;              // [N, AD]
    float* outV = outA + (size_t)NA * AD;              // [N, 1]
    float* outR = outV + (size_t)NA;                   // [N, 3]

    cudaFuncSetAttribute(kfused, cudaFuncAttributeMaxDynamicSharedMemorySize,
                         FUSED_SMEM);

    kfused<<<NB, NT, FUSED_SMEM>>>(states, noise, W1, b1, W2, b2, Wc, bc,
                                   Wg, bg, Wp, bp, Wv, bv, Wr, br,
                                   outH, outA, outV, outR);
}